// round 1
// baseline (speedup 1.0000x reference)
#include <cuda_runtime.h>
#include <math.h>

// Problem constants (fixed shapes from setup_inputs)
#define BS 4
#define PCH 256
#define GCH 64
#define NCLS 81
#define HW 262144            // 512*512
#define NWORDS (HW / 32)     // 8192 bitpack words per mask row

#define SIZE_THRS 1.0f
#define CLS_SCORE_THR 0.5f
#define IOU_THR 0.5f

// ---------------- scratch (static device memory; no allocation) ----------------
__device__ float    g_score[BS * PCH];
__device__ int      g_cls[BS * PCH];
__device__ int      g_active[BS * PCH];
__device__ int      g_any_active;
__device__ int      g_psum[BS * PCH];
__device__ int      g_tsum[BS * GCH];
__device__ int      g_intp[BS * PCH * GCH];
__device__ unsigned g_tbits[BS * GCH * NWORDS];   // 8 MB bitpacked target masks

// ---------------- k0: reset ----------------
__global__ void k0_init() {
    g_any_active = 0;
}

// ---------------- k1: score / class / active flag from logits ----------------
__global__ void k1_score(const float* __restrict__ logits) {
    int i = blockIdx.x * blockDim.x + threadIdx.x;   // i = b*PCH + p
    if (i >= BS * PCH) return;
    const float* row = logits + (size_t)i * NCLS;
    float m = -1e30f;
    int cls = 0;
    for (int c = 0; c < NCLS; c++) {
        float v = row[c];
        if (v > m) { m = v; cls = c; }   // first max kept (strict >) == jnp.argmax
    }
    float s = 0.0f;
    for (int c = 0; c < NCLS; c++) s += expf(row[c] - m);
    float score = 1.0f / s;              // max softmax prob
    g_score[i] = score;
    g_cls[i] = cls;
    int act = (cls != 0) && (score >= CLS_SCORE_THR);
    g_active[i] = act;
    if (act) atomicOr(&g_any_active, 1);
}

// ---------------- k2: bitpack target masks + tgt_sum (gated) ----------------
// one block per (b,g) row, 256 threads
__global__ void k2_tbits(const float* __restrict__ tgt) {
    if (!g_any_active) return;   // the common case: zero work
    int row = blockIdx.x;        // 0..255 = b*GCH + g
    int lane = threadIdx.x & 31;
    int warp = threadIdx.x >> 5; // 8 warps
    const float* src = tgt + (size_t)row * HW;
    unsigned* dst = g_tbits + (size_t)row * NWORDS;
    int cnt = 0;
    for (int wi = warp; wi < NWORDS; wi += 8) {
        float v = src[wi * 32 + lane];
        int bit = (v > 0.5f);
        unsigned w = __ballot_sync(0xFFFFFFFFu, bit);
        if (lane == 0) dst[wi] = w;
        cnt += bit;
    }
    __shared__ int s_cnt;
    if (threadIdx.x == 0) s_cnt = 0;
    __syncthreads();
    // warp reduce then one atomic per warp
    for (int off = 16; off; off >>= 1) cnt += __shfl_xor_sync(0xFFFFFFFFu, cnt, off);
    if (lane == 0) atomicAdd(&s_cnt, cnt);
    __syncthreads();
    if (threadIdx.x == 0) g_tsum[row] = s_cnt;
}

// ---------------- k3: per active pred row: psum + 64 intersections ----------------
// one block per (b,p), 256 threads (8 warps)
__global__ void k3_intersect(const float* __restrict__ pred) {
    int i = blockIdx.x;          // b*PCH + p
    if (!g_active[i]) return;    // common case: all blocks exit immediately
    int b = i >> 8;
    int lane = threadIdx.x & 31;
    int warp = threadIdx.x >> 5;
    const float* src = pred + (size_t)i * HW;
    const unsigned* tb = g_tbits + (size_t)(b * GCH) * NWORDS;

    __shared__ int s_acc[GCH];
    __shared__ int s_psum;
    if (threadIdx.x < GCH) s_acc[threadIdx.x] = 0;
    if (threadIdx.x == 0) s_psum = 0;
    __syncthreads();

    int a0 = 0, a1 = 0, pcnt = 0;
    int g0 = lane, g1 = lane + 32;
    for (int wi = warp; wi < NWORDS; wi += 8) {
        float v = src[wi * 32 + lane];
        int bit = (v > 0.5f);
        unsigned pw = __ballot_sync(0xFFFFFFFFu, bit);
        pcnt += bit;
        a0 += __popc(pw & tb[(size_t)g0 * NWORDS + wi]);
        a1 += __popc(pw & tb[(size_t)g1 * NWORDS + wi]);
    }
    atomicAdd(&s_acc[g0], a0);
    atomicAdd(&s_acc[g1], a1);
    for (int off = 16; off; off >>= 1) pcnt += __shfl_xor_sync(0xFFFFFFFFu, pcnt, off);
    if (lane == 0) atomicAdd(&s_psum, pcnt);
    __syncthreads();
    if (threadIdx.x < GCH) g_intp[i * GCH + threadIdx.x] = s_acc[threadIdx.x];
    if (threadIdx.x == 0) g_psum[i] = s_psum;
}

// ---------------- k4: greedy matching + final metrics ----------------
// 1 block, 128 threads: warp w handles batch w
__global__ void k4_match(const int* __restrict__ tcls, float* __restrict__ out) {
    __shared__ float s_tp[BS], s_fp[BS];
    int warp = threadIdx.x >> 5;
    int lane = threadIdx.x & 31;

    if (warp < BS) {
        int b = warp;
        float sc[8];
        unsigned vis = 0;   // per-lane visited bits for its 8 preds (p = k*32 + lane)
        for (int k = 0; k < 8; k++) sc[k] = g_score[b * PCH + k * 32 + lane];

        float tp = 0.0f, fp = 0.0f;
        unsigned long long claimed = 0ull;

        for (int iter = 0; iter < PCH; iter++) {
            // ---- select next pred: highest score, ties -> lowest index (stable argsort) ----
            float bv = -1e30f;
            int bi = 1 << 30;
            for (int k = 0; k < 8; k++) {
                if (!((vis >> k) & 1u)) {
                    int p = k * 32 + lane;
                    float v = sc[k];
                    if (v > bv || (v == bv && p < bi)) { bv = v; bi = p; }
                }
            }
            for (int off = 16; off; off >>= 1) {
                float ov = __shfl_xor_sync(0xFFFFFFFFu, bv, off);
                int   oi = __shfl_xor_sync(0xFFFFFFFFu, bi, off);
                if (ov > bv || (ov == bv && oi < bi)) { bv = ov; bi = oi; }
            }
            // all remaining preds have score < thr (or none left): all skips -> done
            if (bv < CLS_SCORE_THR) break;

            int pk = bi;
            if (lane == (pk & 31)) vis |= 1u << (pk >> 5);   // mark visited (owner lane)

            int idx = b * PCH + pk;
            int cls = g_cls[idx];
            int psum = g_psum[idx];
            bool skip = (cls == 0) || ((float)psum < SIZE_THRS);
            if (skip) continue;

            // ---- argmax over 64 IoUs (claimed columns read as 0), ties -> lowest g ----
            float ps = (float)psum;
            int ga = lane, gb_ = lane + 32;
            float it0 = (float)g_intp[idx * GCH + ga];
            float it1 = (float)g_intp[idx * GCH + gb_];
            float ts0 = (float)g_tsum[b * GCH + ga];
            float ts1 = (float)g_tsum[b * GCH + gb_];
            float iou0 = ((claimed >> ga) & 1ull) ? 0.0f : it0 / (ps + ts0 - it0 + 0.01f);
            float iou1 = ((claimed >> gb_) & 1ull) ? 0.0f : it1 / (ps + ts1 - it1 + 0.01f);
            float mv = iou0; int mg = ga;
            if (iou1 > mv) { mv = iou1; mg = gb_; }
            for (int off = 16; off; off >>= 1) {
                float ov = __shfl_xor_sync(0xFFFFFFFFu, mv, off);
                int   og = __shfl_xor_sync(0xFFFFFFFFu, mg, off);
                if (ov > mv || (ov == mv && og < mg)) { mv = ov; mg = og; }
            }
            bool hit = (mv >= IOU_THR) && (cls == tcls[b * GCH + mg]);
            if (hit) { tp += 1.0f; claimed |= (1ull << mg); }
            else     { fp += 1.0f; }
        }
        if (lane == 0) { s_tp[b] = tp; s_fp[b] = fp; }
    }
    __syncthreads();

    if (threadIdx.x == 0) {
        float tp = 0.0f, fp = 0.0f;
        for (int b = 0; b < BS; b++) { tp += s_tp[b]; fp += s_fp[b]; }
        float tot = 0.0f;
        for (int i = 0; i < BS * GCH; i++) tot += (tcls[i] > 0) ? 1.0f : 0.0f;
        out[0] = tp / (tp + fp + 0.001f);    // precision
        out[1] = tp / (tot + 0.001f);        // recall
        out[2] = tp / (tot + fp + 0.001f);   // accuracy
    }
}

extern "C" void kernel_launch(void* const* d_in, const int* in_sizes, int n_in,
                              void* d_out, int out_size) {
    const float* pred_masks   = (const float*)d_in[0];
    const float* target_masks = (const float*)d_in[1];
    const float* pred_logits  = (const float*)d_in[2];
    const int*   target_cls   = (const int*)d_in[3];
    float* out = (float*)d_out;

    k0_init<<<1, 1>>>();
    k1_score<<<BS, PCH>>>(pred_logits);
    k2_tbits<<<BS * GCH, 256>>>(target_masks);
    k3_intersect<<<BS * PCH, 256>>>(pred_masks);
    k4_match<<<1, 128>>>(target_cls, out);
}

// round 2
// speedup vs baseline: 1.8221x; 1.8221x over previous
#include <cuda_runtime.h>
#include <math.h>

// Fixed shapes from setup_inputs
#define BS 4
#define PCH 256
#define GCH 64
#define NCLS 81
#define HW 262144            // 512*512
#define NWORDS (HW / 32)     // 8192 32-bit words per mask row

#define SIZE_THRS 1.0f
#define CLS_SCORE_THR 0.5f
#define IOU_THR 0.5f

// ---- static device scratch (no allocations) ----
__device__ int   g_counter = 0;            // completion counter; last block resets -> graph-replay safe
__device__ float g_score[BS * PCH];
__device__ int   g_cls[BS * PCH];
__device__ int   g_psum[BS * PCH];         // written only by active blocks
__device__ int   g_tsum[BS * GCH];         // written only by active blocks (idempotent per batch)
__device__ int   g_intp[BS * PCH * GCH];   // written only by active blocks

// Single fused kernel: grid = BS*PCH blocks (one per prediction), 256 threads.
// Phase 1: block computes its own pred's max-softmax score + argmax class (local, no deps).
// Phase 2 (only if active: cls!=0 && score>=0.5): bitpack own pred row to SMEM, compute
//          psum + 64 popc intersections + per-batch tgt sums straight from the raw masks.
// Phase 3: threadfence + completion counter; LAST block replicates the reference's greedy
//          scan exactly (stable score sort, first-index argmax ties, GT claiming) and
//          writes precision/recall/accuracy.
__global__ void eval_kernel(const float* __restrict__ pred,
                            const float* __restrict__ tgt,
                            const float* __restrict__ logits,
                            const int*   __restrict__ tcls,
                            float* __restrict__ out) {
    int i = blockIdx.x;            // b*PCH + p
    int b = i >> 8;
    int tid = threadIdx.x, lane = tid & 31, warp = tid >> 5;

    __shared__ float s_score;
    __shared__ int   s_cls;
    __shared__ unsigned s_pbits[NWORDS];   // 32 KB: this pred's bitpacked mask (active path only)

    // ---------- phase 1: score / class (warp 0 only) ----------
    if (warp == 0) {
        const float* row = logits + (size_t)i * NCLS;
        float m = -1e30f; int mc = 1 << 30;
        float vals[3];
        #pragma unroll
        for (int k = 0; k < 3; k++) {
            int c = lane + k * 32;
            float v = (c < NCLS) ? row[c] : -1e30f;
            vals[k] = v;
            if (v > m) { m = v; mc = c; }        // ascending c, strict > == jnp.argmax ties
        }
        #pragma unroll
        for (int off = 16; off; off >>= 1) {
            float ov = __shfl_xor_sync(0xFFFFFFFFu, m, off);
            int   oc = __shfl_xor_sync(0xFFFFFFFFu, mc, off);
            if (ov > m || (ov == m && oc < mc)) { m = ov; mc = oc; }
        }
        float s = 0.0f;
        #pragma unroll
        for (int k = 0; k < 3; k++) {
            int c = lane + k * 32;
            if (c < NCLS) s += expf(vals[k] - m);
        }
        #pragma unroll
        for (int off = 16; off; off >>= 1) s += __shfl_xor_sync(0xFFFFFFFFu, s, off);
        if (lane == 0) {
            float score = 1.0f / s;              // max softmax prob
            s_score = score; s_cls = mc;
            g_score[i] = score; g_cls[i] = mc;
        }
    }
    __syncthreads();
    bool active = (s_cls != 0) && (s_score >= CLS_SCORE_THR);

    // ---------- phase 2: intersections (active preds only; common case: skipped) ----------
    if (active) {
        const float* psrc = pred + (size_t)i * HW;
        // pass A: bitpack this pred row into shared, count psum
        int pcnt = 0;
        for (int wi = warp; wi < NWORDS; wi += 8) {
            float v = psrc[wi * 32 + lane];
            int bit = (v > 0.5f);
            unsigned w = __ballot_sync(0xFFFFFFFFu, bit);
            if (lane == 0) s_pbits[wi] = w;
            pcnt += bit;
        }
        __shared__ int s_ps;
        if (tid == 0) s_ps = 0;
        __syncthreads();
        #pragma unroll
        for (int off = 16; off; off >>= 1) pcnt += __shfl_xor_sync(0xFFFFFFFFu, pcnt, off);
        if (lane == 0) atomicAdd(&s_ps, pcnt);
        __syncthreads();
        if (tid == 0) g_psum[i] = s_ps;

        // pass B: each warp handles 8 GT rows: intersection popc + target sum
        const float* tbase = tgt + (size_t)(b * GCH) * HW;
        for (int gi = 0; gi < 8; gi++) {
            int g = warp + gi * 8;
            const float* ts = tbase + (size_t)g * HW;
            int icnt = 0, tcnt = 0;
            for (int wi = 0; wi < NWORDS; wi++) {
                float v = ts[wi * 32 + lane];
                int bit = (v > 0.5f);
                unsigned tw = __ballot_sync(0xFFFFFFFFu, bit);
                icnt += __popc(tw & s_pbits[wi]);    // warp-uniform
                tcnt += bit;
            }
            #pragma unroll
            for (int off = 16; off; off >>= 1) tcnt += __shfl_xor_sync(0xFFFFFFFFu, tcnt, off);
            if (lane == 0) {
                g_intp[i * GCH + g] = icnt;
                g_tsum[b * GCH + g] = tcnt;          // idempotent across active blocks of batch b
            }
        }
    }

    // ---------- phase 3: completion counter; last block does the greedy match ----------
    __threadfence();
    __shared__ bool s_isLast;
    if (tid == 0) {
        int t = atomicAdd(&g_counter, 1);
        s_isLast = (t == (int)gridDim.x - 1);
    }
    __syncthreads();
    if (!s_isLast) return;
    if (tid == 0) g_counter = 0;                     // reset for next graph replay

    // greedy match: warp w handles batch w (threads 128..255 idle but join syncthreads)
    __shared__ float s_tp[BS], s_fp[BS];
    if (warp < BS) {
        int bb = warp;
        float sc[8];
        unsigned vis = 0;
        #pragma unroll
        for (int k = 0; k < 8; k++) sc[k] = g_score[bb * PCH + k * 32 + lane];

        float tp = 0.0f, fp = 0.0f;
        unsigned long long claimed = 0ull;

        for (int iter = 0; iter < PCH; iter++) {
            // next pred: highest score, ties -> lowest index (stable argsort(-score))
            float bv = -1e30f; int bi = 1 << 30;
            #pragma unroll
            for (int k = 0; k < 8; k++) {
                if (!((vis >> k) & 1u)) {
                    int p = k * 32 + lane;
                    float v = sc[k];
                    if (v > bv || (v == bv && p < bi)) { bv = v; bi = p; }
                }
            }
            #pragma unroll
            for (int off = 16; off; off >>= 1) {
                float ov = __shfl_xor_sync(0xFFFFFFFFu, bv, off);
                int   oi = __shfl_xor_sync(0xFFFFFFFFu, bi, off);
                if (ov > bv || (ov == bv && oi < bi)) { bv = ov; bi = oi; }
            }
            if (bv < CLS_SCORE_THR) break;           // all remaining preds are skips

            int pk = bi;
            if (lane == (pk & 31)) vis |= 1u << (pk >> 5);

            int idx = bb * PCH + pk;
            int cls = g_cls[idx];
            int psum = g_psum[idx];
            bool skip = (cls == 0) || ((float)psum < SIZE_THRS);
            if (skip) continue;

            // argmax over 64 IoUs, claimed cols read 0, ties -> lowest g (jnp.argmax)
            float ps = (float)psum;
            int ga = lane, gb_ = lane + 32;
            float it0 = (float)g_intp[idx * GCH + ga];
            float it1 = (float)g_intp[idx * GCH + gb_];
            float ts0 = (float)g_tsum[bb * GCH + ga];
            float ts1 = (float)g_tsum[bb * GCH + gb_];
            float iou0 = ((claimed >> ga)  & 1ull) ? 0.0f : it0 / (ps + ts0 - it0 + 0.01f);
            float iou1 = ((claimed >> gb_) & 1ull) ? 0.0f : it1 / (ps + ts1 - it1 + 0.01f);
            float mv = iou0; int mg = ga;
            if (iou1 > mv) { mv = iou1; mg = gb_; }
            #pragma unroll
            for (int off = 16; off; off >>= 1) {
                float ov = __shfl_xor_sync(0xFFFFFFFFu, mv, off);
                int   og = __shfl_xor_sync(0xFFFFFFFFu, mg, off);
                if (ov > mv || (ov == mv && og < mg)) { mv = ov; mg = og; }
            }
            bool hit = (mv >= IOU_THR) && (cls == tcls[bb * GCH + mg]);
            if (hit) { tp += 1.0f; claimed |= (1ull << mg); }
            else     { fp += 1.0f; }
        }
        if (lane == 0) { s_tp[bb] = tp; s_fp[bb] = fp; }
    }
    __syncthreads();

    if (tid == 0) {
        float tp = 0.0f, fp = 0.0f;
        #pragma unroll
        for (int bb = 0; bb < BS; bb++) { tp += s_tp[bb]; fp += s_fp[bb]; }
        float tot = 0.0f;
        for (int j = 0; j < BS * GCH; j++) tot += (tcls[j] > 0) ? 1.0f : 0.0f;
        out[0] = tp / (tp + fp + 0.001f);    // precision
        out[1] = tp / (tot + 0.001f);        // recall
        out[2] = tp / (tot + fp + 0.001f);   // accuracy
    }
}

extern "C" void kernel_launch(void* const* d_in, const int* in_sizes, int n_in,
                              void* d_out, int out_size) {
    const float* pred_masks   = (const float*)d_in[0];
    const float* target_masks = (const float*)d_in[1];
    const float* pred_logits  = (const float*)d_in[2];
    const int*   target_cls   = (const int*)d_in[3];
    float* out = (float*)d_out;

    eval_kernel<<<BS * PCH, 256>>>(pred_masks, target_masks, pred_logits, target_cls, out);
}

// round 3
// speedup vs baseline: 2.1445x; 1.1770x over previous
#include <cuda_runtime.h>
#include <math.h>

// Fixed shapes from setup_inputs
#define BS 4
#define PCH 256
#define GCH 64
#define NCLS 81
#define HW 262144            // 512*512
#define NWORDS (HW / 32)     // 8192 32-bit words per mask row

#define SIZE_THRS 1.0f
#define CLS_SCORE_THR 0.5f
#define IOU_THR 0.5f

#define NBLK 64
#define NTHR 512              // 16 warps/block, 1 pred per warp -> 64*16 = 1024 preds

// ---- static device scratch (no allocations) ----
__device__ int   g_counter = 0;            // completion counter; last block resets (graph-replay safe)
__device__ float g_score[BS * PCH];
__device__ int   g_cls[BS * PCH];
__device__ int   g_psum[BS * PCH];         // written only for active preds
__device__ int   g_tsum[BS * GCH];         // written only by active preds (idempotent per batch)
__device__ int   g_intp[BS * PCH * GCH];   // written only for active preds

__global__ void __launch_bounds__(NTHR, 2)
eval_kernel(const float* __restrict__ pred,
            const float* __restrict__ tgt,
            const float* __restrict__ logits,
            const int*   __restrict__ tcls,
            float* __restrict__ out) {
    int tid  = threadIdx.x;
    int lane = tid & 31;
    int warp = tid >> 5;                       // 0..15
    int i    = blockIdx.x * 16 + warp;         // prediction index: b*PCH + p
    int b    = i >> 8;

    // ---------- phase 1: per-warp score / class from 81 logits ----------
    const float* row = logits + (size_t)i * NCLS;
    float m = -1e30f; int mc = 1 << 30;
    float vals[3];
    #pragma unroll
    for (int k = 0; k < 3; k++) {
        int c = lane + k * 32;
        float v = (c < NCLS) ? row[c] : -1e30f;
        vals[k] = v;
        if (v > m) { m = v; mc = c; }          // ascending c, strict > == jnp.argmax ties
    }
    #pragma unroll
    for (int off = 16; off; off >>= 1) {
        float ov = __shfl_xor_sync(0xFFFFFFFFu, m, off);
        int   oc = __shfl_xor_sync(0xFFFFFFFFu, mc, off);
        if (ov > m || (ov == m && oc < mc)) { m = ov; mc = oc; }
    }
    float s = 0.0f;
    #pragma unroll
    for (int k = 0; k < 3; k++) {
        int c = lane + k * 32;
        if (c < NCLS) s += expf(vals[k] - m);
    }
    #pragma unroll
    for (int off = 16; off; off >>= 1) s += __shfl_xor_sync(0xFFFFFFFFu, s, off);
    float score = 1.0f / s;                    // max softmax prob (all lanes have it)
    if (lane == 0) { g_score[i] = score; g_cls[i] = mc; }

    bool active = (mc != 0) && (score >= CLS_SCORE_THR);

    // ---------- phase 2: rare active path (whole warp; correctness fallback) ----------
    if (active) {
        const float* psrc = pred + (size_t)i * HW;
        // psum
        int pcnt = 0;
        for (int wi = 0; wi < NWORDS; wi++) {
            float v = psrc[wi * 32 + lane];
            pcnt += (v > 0.5f);
        }
        #pragma unroll
        for (int off = 16; off; off >>= 1) pcnt += __shfl_xor_sync(0xFFFFFFFFu, pcnt, off);
        if (lane == 0) g_psum[i] = pcnt;
        // 64 intersections via inline double-ballot (re-reads pred row per GT; rare path)
        const float* tbase = tgt + (size_t)(b * GCH) * HW;
        for (int g = 0; g < GCH; g++) {
            const float* ts = tbase + (size_t)g * HW;
            int icnt = 0, tcnt = 0;
            for (int wi = 0; wi < NWORDS; wi++) {
                float pv = psrc[wi * 32 + lane];
                float tv = ts[wi * 32 + lane];
                unsigned pw = __ballot_sync(0xFFFFFFFFu, pv > 0.5f);
                int tb_ = (tv > 0.5f);
                unsigned tw = __ballot_sync(0xFFFFFFFFu, tb_);
                icnt += __popc(pw & tw);       // warp-uniform
                tcnt += tb_;
            }
            #pragma unroll
            for (int off = 16; off; off >>= 1) tcnt += __shfl_xor_sync(0xFFFFFFFFu, tcnt, off);
            if (lane == 0) {
                g_intp[i * GCH + g] = icnt;
                g_tsum[b * GCH + g] = tcnt;    // idempotent across active preds of batch b
            }
        }
    }

    // ---------- phase 3: one fence + one atomic per block; last block matches ----------
    __syncthreads();                           // orders all warps' global writes (cumulative)
    __shared__ bool s_isLast;
    if (tid == 0) {
        __threadfence();                       // release: block's writes visible grid-wide
        int t = atomicAdd(&g_counter, 1);
        s_isLast = (t == NBLK - 1);
    }
    __syncthreads();
    if (!s_isLast) return;
    if (tid == 0) g_counter = 0;               // reset for next graph replay
    __threadfence();                           // acquire: see all blocks' writes

    // greedy match: warp w handles batch w (warps 4..15 idle, join syncthreads)
    __shared__ float s_tp[BS], s_fp[BS];
    if (warp < BS) {
        int bb = warp;
        float sc[8];
        unsigned vis = 0;
        #pragma unroll
        for (int k = 0; k < 8; k++) sc[k] = g_score[bb * PCH + k * 32 + lane];

        float tp = 0.0f, fp = 0.0f;
        unsigned long long claimed = 0ull;

        for (int iter = 0; iter < PCH; iter++) {
            // next pred: highest score, ties -> lowest index (stable argsort(-score))
            float bv = -1e30f; int bi = 1 << 30;
            #pragma unroll
            for (int k = 0; k < 8; k++) {
                if (!((vis >> k) & 1u)) {
                    int p = k * 32 + lane;
                    float v = sc[k];
                    if (v > bv || (v == bv && p < bi)) { bv = v; bi = p; }
                }
            }
            #pragma unroll
            for (int off = 16; off; off >>= 1) {
                float ov = __shfl_xor_sync(0xFFFFFFFFu, bv, off);
                int   oi = __shfl_xor_sync(0xFFFFFFFFu, bi, off);
                if (ov > bv || (ov == bv && oi < bi)) { bv = ov; bi = oi; }
            }
            if (bv < CLS_SCORE_THR) break;     // all remaining preds are skips

            int pk = bi;
            if (lane == (pk & 31)) vis |= 1u << (pk >> 5);

            int idx = bb * PCH + pk;
            int cls = g_cls[idx];
            int psum = g_psum[idx];
            bool skip = (cls == 0) || ((float)psum < SIZE_THRS);
            if (skip) continue;

            // argmax over 64 IoUs, claimed cols read 0, ties -> lowest g (jnp.argmax)
            float ps = (float)psum;
            int ga = lane, gb_ = lane + 32;
            float it0 = (float)g_intp[idx * GCH + ga];
            float it1 = (float)g_intp[idx * GCH + gb_];
            float ts0 = (float)g_tsum[bb * GCH + ga];
            float ts1 = (float)g_tsum[bb * GCH + gb_];
            float iou0 = ((claimed >> ga)  & 1ull) ? 0.0f : it0 / (ps + ts0 - it0 + 0.01f);
            float iou1 = ((claimed >> gb_) & 1ull) ? 0.0f : it1 / (ps + ts1 - it1 + 0.01f);
            float mv = iou0; int mg = ga;
            if (iou1 > mv) { mv = iou1; mg = gb_; }
            #pragma unroll
            for (int off = 16; off; off >>= 1) {
                float ov = __shfl_xor_sync(0xFFFFFFFFu, mv, off);
                int   og = __shfl_xor_sync(0xFFFFFFFFu, mg, off);
                if (ov > mv || (ov == mv && og < mg)) { mv = ov; mg = og; }
            }
            bool hit = (mv >= IOU_THR) && (cls == tcls[bb * GCH + mg]);
            if (hit) { tp += 1.0f; claimed |= (1ull << mg); }
            else     { fp += 1.0f; }
        }
        if (lane == 0) { s_tp[bb] = tp; s_fp[bb] = fp; }
    }
    __syncthreads();

    if (tid == 0) {
        float tp = 0.0f, fp = 0.0f;
        #pragma unroll
        for (int bb = 0; bb < BS; bb++) { tp += s_tp[bb]; fp += s_fp[bb]; }
        float tot = 0.0f;
        for (int j = 0; j < BS * GCH; j++) tot += (tcls[j] > 0) ? 1.0f : 0.0f;
        out[0] = tp / (tp + fp + 0.001f);    // precision
        out[1] = tp / (tot + 0.001f);        // recall
        out[2] = tp / (tot + fp + 0.001f);   // accuracy
    }
}

extern "C" void kernel_launch(void* const* d_in, const int* in_sizes, int n_in,
                              void* d_out, int out_size) {
    const float* pred_masks   = (const float*)d_in[0];
    const float* target_masks = (const float*)d_in[1];
    const float* pred_logits  = (const float*)d_in[2];
    const int*   target_cls   = (const int*)d_in[3];
    float* out = (float*)d_out;

    eval_kernel<<<NBLK, NTHR>>>(pred_masks, target_masks, pred_logits, target_cls, out);
}

// round 4
// speedup vs baseline: 2.6728x; 1.2463x over previous
#include <cuda_runtime.h>
#include <math.h>

// Fixed shapes from setup_inputs
#define BS 4
#define PCH 256
#define GCH 64
#define NCLS 81
#define HW 262144            // 512*512
#define NWORDS (HW / 32)

#define SIZE_THRS 1.0f
#define CLS_SCORE_THR 0.5f
#define IOU_THR 0.5f

#define NBLK 64
#define NTHR 512             // 16 warps/block, 1 pred per warp -> 1024 preds

// ---- static device scratch (zero-initialized; no allocations) ----
// Unwritten entries read as 0: score=0 (<thr, sorts last, hit by break),
// cls=0 (skip) -- provably equivalent to the reference's full scan.
__device__ int   g_counter = 0;
__device__ int   g_any     = 0;
__device__ float g_score[BS * PCH];
__device__ int   g_cls[BS * PCH];
__device__ int   g_psum[BS * PCH];
__device__ int   g_tsum[BS * GCH];
__device__ int   g_intp[BS * PCH * GCH];

__global__ void __launch_bounds__(NTHR)
eval_kernel(const float* __restrict__ pred,
            const float* __restrict__ tgt,
            const float* __restrict__ logits,
            const int*   __restrict__ tcls,
            float* __restrict__ out) {
    int tid  = threadIdx.x;
    int lane = tid & 31;
    int warp = tid >> 5;                   // 0..15
    int i    = blockIdx.x * 16 + warp;     // prediction index: b*PCH + p
    int b    = i >> 8;

    // ---------- phase 1: fused online softmax-max + argmax over 81 logits ----------
    const float* row = logits + (size_t)i * NCLS;
    // lane candidates: c = lane, lane+32, lane+64(<81)
    float m; int mc; float s;
    {
        float v0 = row[lane];
        float v1 = row[lane + 32];
        m = v0; mc = lane; s = 1.0f;
        if (v1 > m) { s = s * __expf(m - v1) + 1.0f; m = v1; mc = lane + 32; }
        else        { s += __expf(v1 - m); }
        if (lane + 64 < NCLS) {
            float v2 = row[lane + 64];
            if (v2 > m) { s = s * __expf(m - v2) + 1.0f; m = v2; mc = lane + 64; }
            else        { s += __expf(v2 - m); }
        }
    }
    #pragma unroll
    for (int off = 16; off; off >>= 1) {
        float om = __shfl_xor_sync(0xFFFFFFFFu, m,  off);
        float os = __shfl_xor_sync(0xFFFFFFFFu, s,  off);
        int   oc = __shfl_xor_sync(0xFFFFFFFFu, mc, off);
        if (om > m) { s = s * __expf(m - om) + os; m = om; mc = oc; }
        else {
            s += os * __expf(om - m);              // om==m -> exp(0)=1, exact
            if (om == m && oc < mc) mc = oc;       // first-index tie (jnp.argmax)
        }
    }
    float score = 1.0f / s;                        // max softmax prob
    bool active = (mc != 0) && (score >= CLS_SCORE_THR);

    // ---------- phase 2: rare active path (correctness fallback; zero work normally) ----------
    if (active) {
        if (lane == 0) {
            g_score[i] = score;
            g_cls[i]   = mc;
            atomicExch(&g_any, 1);
        }
        const float* psrc = pred + (size_t)i * HW;
        int pcnt = 0;
        for (int wi = 0; wi < NWORDS; wi++) pcnt += (psrc[wi * 32 + lane] > 0.5f);
        #pragma unroll
        for (int off = 16; off; off >>= 1) pcnt += __shfl_xor_sync(0xFFFFFFFFu, pcnt, off);
        if (lane == 0) g_psum[i] = pcnt;

        const float* tbase = tgt + (size_t)(b * GCH) * HW;
        for (int g = 0; g < GCH; g++) {
            const float* ts = tbase + (size_t)g * HW;
            int icnt = 0, tcnt = 0;
            for (int wi = 0; wi < NWORDS; wi++) {
                unsigned pw = __ballot_sync(0xFFFFFFFFu, psrc[wi * 32 + lane] > 0.5f);
                int tb_ = (ts[wi * 32 + lane] > 0.5f);
                unsigned tw = __ballot_sync(0xFFFFFFFFu, tb_);
                icnt += __popc(pw & tw);
                tcnt += tb_;
            }
            #pragma unroll
            for (int off = 16; off; off >>= 1) tcnt += __shfl_xor_sync(0xFFFFFFFFu, tcnt, off);
            if (lane == 0) {
                g_intp[i * GCH + g] = icnt;
                g_tsum[b * GCH + g] = tcnt;        // idempotent across active preds of batch b
            }
        }
    }

    // ---------- phase 3: block-done barrier; warp 0 handles grid sync ----------
    __syncthreads();                               // all warps of this block finished
    if (warp != 0) return;                         // warps 1..15 leave immediately

    int isLast = 0;
    if (lane == 0) {
        __threadfence();                           // release (cumulative over syncthreads hb)
        isLast = (atomicAdd(&g_counter, 1) == NBLK - 1);
    }
    isLast = __shfl_sync(0xFFFFFFFFu, isLast, 0);
    if (!isLast) return;

    // ---------- last warp: finalize ----------
    __threadfence();                               // acquire: see all blocks' writes
    int any = g_any;
    if (lane == 0) { g_counter = 0; g_any = 0; }   // reset for next graph replay

    if (!any) {                                    // common path: tp=0 -> all outputs 0
        if (lane == 0) { out[0] = 0.0f; out[1] = 0.0f; out[2] = 0.0f; }
        return;
    }

    // general path: single-warp greedy match, batches sequentially (rare)
    float tp = 0.0f, fp = 0.0f;
    for (int bb = 0; bb < BS; bb++) {
        float sc[8];
        unsigned vis = 0;
        #pragma unroll
        for (int k = 0; k < 8; k++) sc[k] = g_score[bb * PCH + k * 32 + lane];
        unsigned long long claimed = 0ull;

        for (int iter = 0; iter < PCH; iter++) {
            float bv = -1e30f; int bi = 1 << 30;
            #pragma unroll
            for (int k = 0; k < 8; k++) {
                if (!((vis >> k) & 1u)) {
                    int p = k * 32 + lane;
                    float v = sc[k];
                    if (v > bv || (v == bv && p < bi)) { bv = v; bi = p; }
                }
            }
            #pragma unroll
            for (int off = 16; off; off >>= 1) {
                float ov = __shfl_xor_sync(0xFFFFFFFFu, bv, off);
                int   oi = __shfl_xor_sync(0xFFFFFFFFu, bi, off);
                if (ov > bv || (ov == bv && oi < bi)) { bv = ov; bi = oi; }
            }
            if (bv < CLS_SCORE_THR) break;         // remaining preds are all skips

            int pk = bi;
            if (lane == (pk & 31)) vis |= 1u << (pk >> 5);

            int idx = bb * PCH + pk;
            int cls = g_cls[idx];
            int psum = g_psum[idx];
            bool skip = (cls == 0) || ((float)psum < SIZE_THRS);
            if (skip) continue;

            float ps = (float)psum;
            int ga = lane, gb_ = lane + 32;
            float it0 = (float)g_intp[idx * GCH + ga];
            float it1 = (float)g_intp[idx * GCH + gb_];
            float ts0 = (float)g_tsum[bb * GCH + ga];
            float ts1 = (float)g_tsum[bb * GCH + gb_];
            float iou0 = ((claimed >> ga)  & 1ull) ? 0.0f : it0 / (ps + ts0 - it0 + 0.01f);
            float iou1 = ((claimed >> gb_) & 1ull) ? 0.0f : it1 / (ps + ts1 - it1 + 0.01f);
            float mv = iou0; int mg = ga;
            if (iou1 > mv) { mv = iou1; mg = gb_; }
            #pragma unroll
            for (int off = 16; off; off >>= 1) {
                float ov = __shfl_xor_sync(0xFFFFFFFFu, mv, off);
                int   og = __shfl_xor_sync(0xFFFFFFFFu, mg, off);
                if (ov > mv || (ov == mv && og < mg)) { mv = ov; mg = og; }
            }
            bool hit = (mv >= IOU_THR) && (cls == tcls[bb * GCH + mg]);
            if (hit) { tp += 1.0f; claimed |= (1ull << mg); }
            else     { fp += 1.0f; }
        }
    }

    // tot = count of tcls > 0 (warp-parallel over 256 entries)
    int totc = 0;
    #pragma unroll
    for (int k = 0; k < 8; k++) totc += (tcls[k * 32 + lane] > 0);
    #pragma unroll
    for (int off = 16; off; off >>= 1) totc += __shfl_xor_sync(0xFFFFFFFFu, totc, off);

    if (lane == 0) {
        float tot = (float)totc;
        out[0] = tp / (tp + fp + 0.001f);
        out[1] = tp / (tot + 0.001f);
        out[2] = tp / (tot + fp + 0.001f);
    }
}

extern "C" void kernel_launch(void* const* d_in, const int* in_sizes, int n_in,
                              void* d_out, int out_size) {
    const float* pred_masks   = (const float*)d_in[0];
    const float* target_masks = (const float*)d_in[1];
    const float* pred_logits  = (const float*)d_in[2];
    const int*   target_cls   = (const int*)d_in[3];
    float* out = (float*)d_out;

    eval_kernel<<<NBLK, NTHR>>>(pred_masks, target_masks, pred_logits, target_cls, out);
}

// round 5
// speedup vs baseline: 3.4952x; 1.3077x over previous
#include <cuda_runtime.h>
#include <math.h>

// Fixed shapes from setup_inputs
#define BS 4
#define PCH 256
#define GCH 64
#define NCLS 81
#define HW 262144            // 512*512
#define NWORDS (HW / 32)

#define SIZE_THRS 1.0f
#define CLS_SCORE_THR 0.5f
#define IOU_THR 0.5f

#define NBLK 128
#define NTHR 256             // 8 warps/block, 1 pred per warp -> 128*8 = 1024 preds

// ---- static device scratch (zero-initialized; no allocations) ----
// Unwritten entries read 0: score=0 (<thr -> sorts last -> hit by break),
// cls=0 (skip) -- equivalent to the reference's full scan.
__device__ int   g_counter = 0;    // low 16 bits: blocks done; high bits: any-active flags
__device__ float g_score[BS * PCH];
__device__ int   g_cls[BS * PCH];
__device__ int   g_psum[BS * PCH];
__device__ int   g_tsum[BS * GCH];
__device__ int   g_intp[BS * PCH * GCH];

// order-preserving float<->uint for REDUX max
__device__ __forceinline__ unsigned f2key(float f) {
    unsigned b = __float_as_uint(f);
    return (b & 0x80000000u) ? ~b : (b | 0x80000000u);
}
__device__ __forceinline__ float key2f(unsigned k) {
    unsigned b = (k & 0x80000000u) ? (k & 0x7FFFFFFFu) : ~k;
    return __uint_as_float(b);
}

__global__ void __launch_bounds__(NTHR)
eval_kernel(const float* __restrict__ pred,
            const float* __restrict__ tgt,
            const float* __restrict__ logits,
            const int*   __restrict__ tcls,
            float* __restrict__ out) {
    int tid  = threadIdx.x;
    int lane = tid & 31;
    int warp = tid >> 5;                   // 0..7
    int i    = blockIdx.x * 8 + warp;      // prediction index: b*PCH + p
    int b    = i >> 8;

    __shared__ int s_any;
    if (tid == 0) s_any = 0;
    __syncthreads();

    // ---------- phase 1: two-phase softmax-max + argmax over 81 logits ----------
    const float* row = logits + (size_t)i * NCLS;
    float v0 = row[lane];
    float v1 = row[lane + 32];
    bool  has2 = (lane + 64) < NCLS;                 // lanes 0..16
    float v2 = has2 ? row[lane + 64] : -1e30f;

    // warp max via single REDUX over ordered keys
    unsigned k = f2key(v0);
    unsigned k1 = f2key(v1); if (k1 > k) k = k1;
    if (has2) { unsigned k2 = f2key(v2); if (k2 > k) k = k2; }
    unsigned kmax = __reduce_max_sync(0xFFFFFFFFu, k);
    float m = key2f(kmax);

    // argmax: first (lowest) index among ties
    int cand = 0x7FFFFFFF;
    if (has2 && v2 == m) cand = lane + 64;
    if (v1 == m) cand = lane + 32;
    if (v0 == m) cand = lane;
    int mc = (int)__reduce_min_sync(0xFFFFFFFFu, (unsigned)cand);

    // sum of exp(v - m): exactly 81 exps per warp, then pure FADD shfl reduce
    float s = __expf(v0 - m) + __expf(v1 - m);
    if (has2) s += __expf(v2 - m);
    #pragma unroll
    for (int off = 16; off; off >>= 1) s += __shfl_xor_sync(0xFFFFFFFFu, s, off);

    float score = 1.0f / s;                          // max softmax prob
    bool active = (mc != 0) && (score >= CLS_SCORE_THR);

    // ---------- phase 2: rare active path (correctness fallback; zero work normally) ----------
    if (active) {
        if (lane == 0) {
            g_score[i] = score;
            g_cls[i]   = mc;
            s_any = 1;                               // race-benign
        }
        const float* psrc = pred + (size_t)i * HW;
        int pcnt = 0;
        for (int wi = 0; wi < NWORDS; wi++) pcnt += (psrc[wi * 32 + lane] > 0.5f);
        #pragma unroll
        for (int off = 16; off; off >>= 1) pcnt += __shfl_xor_sync(0xFFFFFFFFu, pcnt, off);
        if (lane == 0) g_psum[i] = pcnt;

        const float* tbase = tgt + (size_t)(b * GCH) * HW;
        for (int g = 0; g < GCH; g++) {
            const float* ts = tbase + (size_t)g * HW;
            int icnt = 0, tcnt = 0;
            for (int wi = 0; wi < NWORDS; wi++) {
                unsigned pw = __ballot_sync(0xFFFFFFFFu, psrc[wi * 32 + lane] > 0.5f);
                int tb_ = (ts[wi * 32 + lane] > 0.5f);
                unsigned tw = __ballot_sync(0xFFFFFFFFu, tb_);
                icnt += __popc(pw & tw);
                tcnt += tb_;
            }
            #pragma unroll
            for (int off = 16; off; off >>= 1) tcnt += __shfl_xor_sync(0xFFFFFFFFu, tcnt, off);
            if (lane == 0) {
                g_intp[i * GCH + g] = icnt;
                g_tsum[b * GCH + g] = tcnt;          // idempotent across active preds of batch b
            }
        }
    }

    // ---------- phase 3: block barrier; warp 0 handles grid completion ----------
    __syncthreads();                                 // all warps done (orders their global writes)
    if (warp != 0) return;

    int blockAny = s_any;
    int told = 0;
    if (lane == 0) {
        __threadfence();                             // release
        told = atomicAdd(&g_counter, 1 + (blockAny << 16));
    }
    told = __shfl_sync(0xFFFFFFFFu, told, 0);
    if ((told & 0xFFFF) != NBLK - 1) return;         // not last block

    int any = (told >> 16) | blockAny;
    if (lane == 0) g_counter = 0;                    // reset for next graph replay

    if (!any) {                                      // common path: tp=0 -> all outputs 0
        if (lane == 0) { out[0] = 0.0f; out[1] = 0.0f; out[2] = 0.0f; }
        return;
    }

    // ---------- rare general path: single-warp greedy match over all batches ----------
    __threadfence();                                 // acquire: see all blocks' writes
    float tp = 0.0f, fp = 0.0f;
    for (int bb = 0; bb < BS; bb++) {
        float sc[8];
        unsigned vis = 0;
        #pragma unroll
        for (int kk = 0; kk < 8; kk++) sc[kk] = g_score[bb * PCH + kk * 32 + lane];
        unsigned long long claimed = 0ull;

        for (int iter = 0; iter < PCH; iter++) {
            float bv = -1e30f; int bi = 1 << 30;
            #pragma unroll
            for (int kk = 0; kk < 8; kk++) {
                if (!((vis >> kk) & 1u)) {
                    int p = kk * 32 + lane;
                    float v = sc[kk];
                    if (v > bv || (v == bv && p < bi)) { bv = v; bi = p; }
                }
            }
            #pragma unroll
            for (int off = 16; off; off >>= 1) {
                float ov = __shfl_xor_sync(0xFFFFFFFFu, bv, off);
                int   oi = __shfl_xor_sync(0xFFFFFFFFu, bi, off);
                if (ov > bv || (ov == bv && oi < bi)) { bv = ov; bi = oi; }
            }
            if (bv < CLS_SCORE_THR) break;           // remaining preds are all skips

            int pk = bi;
            if (lane == (pk & 31)) vis |= 1u << (pk >> 5);

            int idx = bb * PCH + pk;
            int cls = g_cls[idx];
            int psum = g_psum[idx];
            bool skip = (cls == 0) || ((float)psum < SIZE_THRS);
            if (skip) continue;

            float ps = (float)psum;
            int ga = lane, gb_ = lane + 32;
            float it0 = (float)g_intp[idx * GCH + ga];
            float it1 = (float)g_intp[idx * GCH + gb_];
            float ts0 = (float)g_tsum[bb * GCH + ga];
            float ts1 = (float)g_tsum[bb * GCH + gb_];
            float iou0 = ((claimed >> ga)  & 1ull) ? 0.0f : it0 / (ps + ts0 - it0 + 0.01f);
            float iou1 = ((claimed >> gb_) & 1ull) ? 0.0f : it1 / (ps + ts1 - it1 + 0.01f);
            float mv = iou0; int mg = ga;
            if (iou1 > mv) { mv = iou1; mg = gb_; }
            #pragma unroll
            for (int off = 16; off; off >>= 1) {
                float ov = __shfl_xor_sync(0xFFFFFFFFu, mv, off);
                int   og = __shfl_xor_sync(0xFFFFFFFFu, mg, off);
                if (ov > mv || (ov == mv && og < mg)) { mv = ov; mg = og; }
            }
            bool hit = (mv >= IOU_THR) && (cls == tcls[bb * GCH + mg]);
            if (hit) { tp += 1.0f; claimed |= (1ull << mg); }
            else     { fp += 1.0f; }
        }
    }

    int totc = 0;
    #pragma unroll
    for (int kk = 0; kk < 8; kk++) totc += (tcls[kk * 32 + lane] > 0);
    #pragma unroll
    for (int off = 16; off; off >>= 1) totc += __shfl_xor_sync(0xFFFFFFFFu, totc, off);

    if (lane == 0) {
        float tot = (float)totc;
        out[0] = tp / (tp + fp + 0.001f);
        out[1] = tp / (tot + 0.001f);
        out[2] = tp / (tot + fp + 0.001f);
    }
}

extern "C" void kernel_launch(void* const* d_in, const int* in_sizes, int n_in,
                              void* d_out, int out_size) {
    const float* pred_masks   = (const float*)d_in[0];
    const float* target_masks = (const float*)d_in[1];
    const float* pred_logits  = (const float*)d_in[2];
    const int*   target_cls   = (const int*)d_in[3];
    float* out = (float*)d_out;

    eval_kernel<<<NBLK, NTHR>>>(pred_masks, target_masks, pred_logits, target_cls, out);
}